// round 1
// baseline (speedup 1.0000x reference)
#include <cuda_runtime.h>
#include <cuda_bf16.h>
#include <cstdint>

// Problem constants (from reference_code)
constexpr int NNB     = 16;        // N_NEIGH
constexpr int NFEAT   = 32;        // N_FEAT
constexpr int ROW     = 3 + 3 * NFEAT;   // 99 features per pair
constexpr int PAIRS   = NNB * NNB - NNB; // 240 off-diagonal pairs
constexpr int PER_C   = PAIRS * ROW;     // 23760 floats per center

__global__ void __launch_bounds__(256)
ang_desc_kernel(const float* __restrict__ atoms_xyz,   // [N_ATOMS,3]
                const float* __restrict__ embed,       // [N_TYPES,32]
                const float* __restrict__ dist,        // [C,16]
                const int*   __restrict__ types,       // [N_ATOMS]
                const int*   __restrict__ i_idx,       // [C]
                const int*   __restrict__ j_idx,       // [C,16]
                float*       __restrict__ out,         // [C,240,99]
                float*       __restrict__ centers_out) // [C]
{
    const int c = blockIdx.x;
    const int t = threadIdx.x;

    __shared__ float s_d[NNB];        // dist row
    __shared__ float s_inv[NNB];      // 1/dist
    __shared__ float s_embi[NFEAT];   // center embedding
    __shared__ float s_embj[NNB * NFEAT]; // neighbor embeddings pre-scaled by 1/d
    __shared__ float s_norm[NNB * NNB];   // d_jk_norm table, indexed by q=j*16+k
    __shared__ float s_x[NNB], s_y[NNB], s_z[NNB];
    __shared__ int   s_aj[NNB];
    __shared__ int   s_tj[NNB];
    __shared__ int   s_ti;

    // ---- Phase A: independent global loads ----
    if (t < NNB) {
        float d = dist[c * NNB + t];
        s_d[t]   = d;
        s_inv[t] = 1.0f / d;
        s_aj[t]  = j_idx[c * NNB + t];
    } else if (t == NNB) {
        int ai = i_idx[c];
        s_ti = types[ai];
        centers_out[c] = (float)ai;
    }
    __syncthreads();

    // ---- Phase B: dependent gathers ----
    if (t < NNB) {
        int a = s_aj[t];
        s_x[t] = atoms_xyz[a * 3 + 0];
        s_y[t] = atoms_xyz[a * 3 + 1];
        s_z[t] = atoms_xyz[a * 3 + 2];
        s_tj[t] = types[a];
    } else if (t >= 32 && t < 64) {
        s_embi[t - 32] = embed[s_ti * NFEAT + (t - 32)];
    }
    __syncthreads();

    // ---- Phase C: build scaled neighbor-embedding table + d_jk_norm ----
    // embj_scaled[nb][f] = embed[type_nb][f] / d[nb]  (serves both e_j and e_k)
    for (int idx = t; idx < NNB * NFEAT; idx += 256) {
        int nb = idx >> 5;
        int f  = idx & 31;
        s_embj[idx] = embed[s_tj[nb] * NFEAT + f] * s_inv[nb];
    }
    {
        int j = t >> 4, k = t & 15;
        float dx = s_x[j] - s_x[k];
        float dy = s_y[j] - s_y[k];
        float dz = s_z[j] - s_z[k];
        float djk = sqrtf(dx * dx + dy * dy + dz * dz);
        float dj = s_d[j], dk = s_d[k];
        float mx = fmaxf(dj, dk), mn = fminf(dj, dk);
        s_norm[t] = (djk - mx + mn) / (2.0f * mn);
    }
    __syncthreads();

    // ---- Phase D: stream 240 rows of 99 floats, warp-per-row ----
    const int warp = t >> 5;
    const int lane = t & 31;
    float* base = out + (size_t)c * PER_C;

    // Lane-constant hoists (f-class pattern per pass is fixed across pairs):
    // pass0 lane>=3 : emb_i[lane-3]
    // pass1 lane< 3 : emb_i[29+lane]
    const float embi_a = s_embi[(lane - 3) & 31];            // used for lane>=3
    const float embi_b = s_embi[(29 + lane) < 32 ? (29 + lane) : 31]; // used for lane<3
    const bool  l0 = (lane == 0), l1 = (lane == 1), l2 = (lane == 2);
    const bool  llt3 = (lane < 3);

    #pragma unroll 2
    for (int p = warp; p < PAIRS; p += 8) {
        int q = p + (p >> 4) + 1;     // flat n*n index skipping the diagonal
        int j = q >> 4;
        int k = q & 15;

        float dj  = s_d[j];
        float dk  = s_d[k];
        float njk = s_norm[q];

        const float* ej = s_embj + j * NFEAT;
        const float* ek = s_embj + k * NFEAT;

        // pass 0: f = lane          -> [d_ij, d_ik, d_jk_norm, emb_i[0..28]]
        float v0 = embi_a;
        if (l2) v0 = njk;
        if (l1) v0 = dk;
        if (l0) v0 = dj;

        // pass 1: f = 32 + lane     -> [emb_i[29..31], e_j[0..28]]
        float v1 = llt3 ? embi_b : ej[(lane - 3) & 31];

        // pass 2: f = 64 + lane     -> [e_j[29..31], e_k[0..28]]
        float v2 = llt3 ? ej[29 + lane] : ek[(lane - 3) & 31];

        float* rb = base + p * ROW;
        rb[lane]      = v0;
        rb[32 + lane] = v1;
        rb[64 + lane] = v2;
        // pass 3: f = 96 + lane (lane<3) -> e_k[29..31]
        if (llt3) rb[96 + lane] = ek[29 + lane];
    }
}

extern "C" void kernel_launch(void* const* d_in, const int* in_sizes, int n_in,
                              void* d_out, int out_size)
{
    const float* atoms_xyz = (const float*)d_in[0];
    const float* embed     = (const float*)d_in[1];
    const float* dist      = (const float*)d_in[2];
    const int*   types     = (const int*)  d_in[3];
    const int*   i_idx     = (const int*)  d_in[4];
    const int*   j_idx     = (const int*)  d_in[5];

    const int C = in_sizes[4];                 // number of centers
    float* out = (float*)d_out;
    float* centers_out = out + (size_t)C * PER_C;

    ang_desc_kernel<<<C, 256>>>(atoms_xyz, embed, dist, types,
                                i_idx, j_idx, out, centers_out);
}